// round 14
// baseline (speedup 1.0000x reference)
#include <cuda_runtime.h>
#include <cuda_fp16.h>
#include <cstdint>

#define B_ 16
#define C_ 256
#define N_ 4096
#define M_ 1024
#define EPS_ 1e-5f
typedef long long ll;

// ---------------- scratch ----------------
__device__ float g_xm[B_ * C_];
__device__ float g_score[B_ * N_];       // pass1: ||x_n||^2 ; pass2: monotone uint key
__device__ int   g_idx[2 * B_ * M_];
__device__ double g_sum[C_];
__device__ double g_sumsq[C_];
__device__ float g_bp[3 * 512];          // packed biases: bq2|bk2|bv2
__device__ float g_bc[C_];               // bconst for final gemm
__device__ float g_l[2 * B_ * N_];       // softmax row sums

__device__ __half g_cat[(ll)B_ * N_ * 768];   // [b][n][ Y_s(256) | Y_g(256) | x(256) ]
__device__ __half g_ctxh[2LL * B_ * M_ * C_]; // [side][b][m][c]
__device__ __half g_Qh[(ll)B_ * N_ * 512];    // [b][n][512]
__device__ __half g_Kh[2LL * B_ * M_ * C_];
__device__ __half g_Vth[2LL * B_ * C_ * M_];  // [side][b][d][m]
__device__ __half g_Sh[2LL * B_ * N_ * M_];   // unnormalized exp scores
__device__ __half g_Ph[(ll)B_ * C_ * N_];     // pre-BN output
__device__ __half g_Wh[6 * C_ * C_];          // Wq_s,Wq_g,Wk_s,Wk_g,Wv_s,Wv_g
__device__ __half g_W3[C_ * 768];             // [Wc_s | Wc_g | Wx]

// ---------------- PTX ----------------
__device__ __forceinline__ void cp16(uint32_t dst, const void* src) {
    asm volatile("cp.async.cg.shared.global [%0], [%1], 16;" :: "r"(dst), "l"(src));
}
__device__ __forceinline__ void cp_commit() { asm volatile("cp.async.commit_group;"); }
template <int Nw> __device__ __forceinline__ void cp_wait() {
    asm volatile("cp.async.wait_group %0;" :: "n"(Nw));
}
__device__ __forceinline__ void ldsm_x4(uint32_t* r, uint32_t a) {
    asm volatile("ldmatrix.sync.aligned.m8n8.x4.shared.b16 {%0,%1,%2,%3}, [%4];"
        : "=r"(r[0]), "=r"(r[1]), "=r"(r[2]), "=r"(r[3]) : "r"(a));
}
__device__ __forceinline__ void ldsm_x2(uint32_t* r, uint32_t a) {
    asm volatile("ldmatrix.sync.aligned.m8n8.x2.shared.b16 {%0,%1}, [%2];"
        : "=r"(r[0]), "=r"(r[1]) : "r"(a));
}
__device__ __forceinline__ void mma_f16(float* c, const uint32_t* a, const uint32_t* b) {
    asm volatile("mma.sync.aligned.m16n8k16.row.col.f32.f16.f16.f32 "
        "{%0,%1,%2,%3}, {%4,%5,%6,%7}, {%8,%9}, {%0,%1,%2,%3};"
        : "+f"(c[0]), "+f"(c[1]), "+f"(c[2]), "+f"(c[3])
        : "r"(a[0]), "r"(a[1]), "r"(a[2]), "r"(a[3]), "r"(b[0]), "r"(b[1]));
}
__device__ __forceinline__ uint32_t ex2_h2(uint32_t u) {
    asm("ex2.approx.f16x2 %0, %0;" : "+r"(u));
    return u;
}

// ---------------- small kernels ----------------
// transpose fp32 [b][c][n] -> fp16 cat x-slot; fused mean + per-point sumsq accumulation
__global__ void transpose_kernel(const float* __restrict__ x) {
    __shared__ float t[32][33];
    __shared__ float ps[32][9];
    __shared__ float ps2[32][9];
    int b = blockIdx.z, n0 = blockIdx.x * 32, c0 = blockIdx.y * 32;
    int tx = threadIdx.x, ty = threadIdx.y;  // (32, 8)
    const float* xp = x + (ll)b * C_ * N_;
    __half* xhp = g_cat + (ll)b * N_ * 768 + 512;
#pragma unroll
    for (int i = 0; i < 32; i += 8)
        t[ty + i][tx] = xp[(ll)(c0 + ty + i) * N_ + n0 + tx];
    __syncthreads();
#pragma unroll
    for (int i = 0; i < 32; i += 8)
        xhp[(ll)(n0 + ty + i) * 768 + c0 + tx] = __float2half_rn(t[tx][ty + i]);
    float s = 0.f;
#pragma unroll
    for (int q = 0; q < 4; q++) s += t[tx][ty * 4 + q];
    ps[tx][ty] = s;
    float s2 = 0.f;
#pragma unroll
    for (int q = 0; q < 4; q++) { float v = t[ty * 4 + q][tx]; s2 += v * v; }
    ps2[tx][ty] = s2;
    __syncthreads();
    if (ty == 0) {
        float tot = 0.f, tot2 = 0.f;
#pragma unroll
        for (int q = 0; q < 8; q++) { tot += ps[tx][q]; tot2 += ps2[tx][q]; }
        atomicAdd(&g_xm[b * C_ + c0 + tx], tot * (1.0f / N_));
        atomicAdd(&g_score[b * N_ + n0 + tx], tot2);
    }
}

// full-grid scoring: warp-per-point over fp16 x; writes monotone uint key in place
__global__ void score2_kernel() {
    int b = blockIdx.y;
    int warp = threadIdx.x >> 5, lane = threadIdx.x & 31;
    int n = blockIdx.x * 8 + warp;
    float mr[8];
    {
        const float4* mp = (const float4*)(g_xm + b * C_);
        float4 m0 = mp[lane * 2], m1 = mp[lane * 2 + 1];
        mr[0] = m0.x; mr[1] = m0.y; mr[2] = m0.z; mr[3] = m0.w;
        mr[4] = m1.x; mr[5] = m1.y; mr[6] = m1.z; mr[7] = m1.w;
    }
    uint4 v = ((const uint4*)(g_cat + ((ll)b * N_ + n) * 768 + 512))[lane];
    float2 f0 = __half22float2(*(__half2*)&v.x);
    float2 f1 = __half22float2(*(__half2*)&v.y);
    float2 f2 = __half22float2(*(__half2*)&v.z);
    float2 f3 = __half22float2(*(__half2*)&v.w);
    float dot = f0.x * mr[0] + f0.y * mr[1] + f1.x * mr[2] + f1.y * mr[3]
              + f2.x * mr[4] + f2.y * mr[5] + f3.x * mr[6] + f3.y * mr[7];
#pragma unroll
    for (int o = 16; o; o >>= 1) dot += __shfl_xor_sync(0xffffffffu, dot, o);
    if (lane == 0) {
        float sc = g_score[b * N_ + n] - 2.f * dot;  // + ||mu||^2 const dropped
        uint32_t u = __float_as_uint(sc);
        u ^= (uint32_t)(((int)u >> 31)) | 0x80000000u;  // monotone float->uint
        ((uint32_t*)g_score)[b * N_ + n] = u;
    }
}

// radix-select: one block per (batch, direction); warp-shfl scan (2 barriers/pass)
__global__ void select_kernel() {
    __shared__ uint32_t sv[N_];
    __shared__ int hist[256];
    __shared__ int wtot[8], woff[8];
    __shared__ int s_digit, s_k, s_cnt, s_base, s_total;
    int b = blockIdx.x, dir = blockIdx.y, t = threadIdx.x;  // 1024 threads
    int lane = t & 31, wid = t >> 5;
    for (int i = t; i < N_; i += 1024) sv[i] = ((const uint32_t*)g_score)[b * N_ + i];
    __syncthreads();

    uint32_t prefix = 0, pmask = 0;
    int k = M_;
    for (int pass = 0; pass < 4; pass++) {
        int shift = 24 - 8 * pass;
        if (t < 256) hist[t] = 0;
        __syncthreads();
        for (int i = t; i < N_; i += 1024) {
            uint32_t v = sv[i];
            if ((v & pmask) == prefix) atomicAdd(&hist[(v >> shift) & 255], 1);
        }
        __syncthreads();
        int val = 0, h = 0;
        if (t < 256) {
            h = hist[t]; val = h;
#pragma unroll
            for (int off = 1; off < 32; off <<= 1) {
                int nv = __shfl_up_sync(0xffffffffu, val, off);
                if (lane >= off) val += nv;
            }
            if (lane == 31) wtot[wid] = val;
        }
        __syncthreads();
        if (t == 0) {
            int acc = 0;
#pragma unroll
            for (int w = 0; w < 8; w++) { woff[w] = acc; acc += wtot[w]; }
            s_total = acc;
        }
        __syncthreads();
        if (t < 256) {
            int incl = val + woff[wid];
            int excl = incl - h;
            int total = s_total;
            if (dir == 0) {
                int above = total - incl, atLeast = total - excl;
                if (atLeast >= k && above < k) { s_digit = t; s_k = k - above; }
            } else {
                if (incl >= k && excl < k) { s_digit = t; s_k = k - excl; }
            }
        }
        __syncthreads();
        prefix |= ((uint32_t)s_digit) << shift;
        pmask |= 0xFFu << shift;
        k = s_k;
        __syncthreads();
    }
    uint32_t T = prefix;
    int keq = k;
    if (t == 0) s_cnt = 0;
    __syncthreads();
    int* dst = g_idx + dir * B_ * M_ + b * M_;
    for (int i = t; i < N_; i += 1024) {
        uint32_t v = sv[i];
        bool strict = (dir == 0) ? (v > T) : (v < T);
        if (strict) dst[atomicAdd(&s_cnt, 1)] = i;
    }
    __syncthreads();
    if (t == 0) { s_base = s_cnt; s_cnt = 0; }
    __syncthreads();
    for (int i = t; i < N_; i += 1024) {
        if (sv[i] == T) {
            int e = atomicAdd(&s_cnt, 1);
            if (e < keq) dst[s_base + e] = i;
        }
    }
}

__global__ void gather_kernel() {
    int side = blockIdx.z, b = blockIdx.y;
    int m = blockIdx.x * 8 + (threadIdx.x >> 5);
    int c8 = threadIdx.x & 31;
    int j = g_idx[side * B_ * M_ + b * M_ + m];
    uint4 v = ((const uint4*)(g_cat + ((ll)b * N_ + j) * 768 + 512))[c8];
    ((uint4*)(g_ctxh + (((ll)side * B_ + b) * M_ + m) * C_))[c8] = v;
}

// pack_w: weights->fp16, biases->g_bp, zero-init l/xm/score/stats
__global__ void pack_w(const float* a0, const float* a1, const float* a2,
                       const float* a3, const float* a4, const float* a5,
                       const float* b0, const float* b1, const float* b2,
                       const float* b3, const float* b4, const float* b5) {
    int i = blockIdx.x * 256 + threadIdx.x;  // 393216 threads
    const float* p[6] = {a0, a1, a2, a3, a4, a5};
    g_Wh[i] = __float2half_rn(p[i >> 16][i & 65535]);
    if (i < 2 * B_ * N_) g_l[i] = 0.f;
    if (i < B_ * N_) g_score[i] = 0.f;
    if (i < B_ * C_) g_xm[i] = 0.f;
    if (i < C_) { g_sum[i] = 0.0; g_sumsq[i] = 0.0; }
    if (i < 1536) {
        const float* q[6] = {b0, b1, b2, b3, b4, b5};
        int grp = i >> 9, k = i & 511;
        g_bp[i] = q[(grp << 1) | (k >> 8)][k & 255];
    }
}

__global__ void combine_w(const float* __restrict__ Wf,
                          const float* __restrict__ Wo_s, const float* __restrict__ Wo_g,
                          const float* __restrict__ bf,
                          const float* __restrict__ bo_s, const float* __restrict__ bo_g) {
    int d = blockIdx.x, t = threadIdx.x;
    __shared__ float wf[512];
    wf[t] = Wf[d * 512 + t];
    wf[t + 256] = Wf[d * 512 + 256 + t];
    __syncthreads();
    float a0 = 0.f, a1 = 0.f;
#pragma unroll 4
    for (int e = 0; e < 256; e++) {
        a0 += wf[e] * Wo_s[e * 256 + t];
        a1 += wf[256 + e] * Wo_g[e * 256 + t];
    }
    g_W3[d * 768 + t] = __float2half_rn(a0);
    g_W3[d * 768 + 256 + t] = __float2half_rn(a1);
    g_W3[d * 768 + 512 + t] = __float2half_rn(wf[t] + wf[256 + t]);
    if (t == 0) {
        float bc = bf[d];
        for (int e = 0; e < 256; e++) bc += wf[e] * bo_s[e] + wf[256 + e] * bo_g[e];
        g_bc[d] = bc;
    }
}

// bn_final with inline finalize (per-block recompute of w,b — L2-cached loads)
__global__ void bn_final(float* __restrict__ out,
                         const float* __restrict__ gamma, const float* __restrict__ beta) {
    int i = blockIdx.x * 256 + threadIdx.x;  // N/4 per (d,b)
    int d = blockIdx.y, b = blockIdx.z;
    double cnt = (double)B_ * N_;
    double mu = g_sum[d] / cnt;
    double var = g_sumsq[d] / cnt - mu * mu;
    float w = gamma[d] * rsqrtf((float)var + EPS_);
    float bb = beta[d] - (float)mu * w;
    ll base = ((ll)b * C_ + d) * N_;
    uint2 raw = ((const uint2*)(g_Ph + base))[i];
    float2 f0 = __half22float2(*(__half2*)&raw.x);
    float2 f1 = __half22float2(*(__half2*)&raw.y);
    float4 o;
    o.x = fmaxf(f0.x * w + bb, 0.f);
    o.y = fmaxf(f0.y * w + bb, 0.f);
    o.z = fmaxf(f1.x * w + bb, 0.f);
    o.w = fmaxf(f1.y * w + bb, 0.f);
    ((float4*)(out + base))[i] = o;
}

// ---------------- fp16 TN GEMM: 3-stage cp.async pipeline ----------------
// EPI: 0 none, 1 ex2(h2)+rowsum (scale pre-folds log2e), 2 div-by-l
__device__ __forceinline__ void load_stage(uint32_t sb, const __half* A, const __half* Bg,
                                           int row0, int col0, int lda, int ldb,
                                           int k0, int tid) {
#pragma unroll
    for (int r = 0; r < 4; r++) {
        int lin = tid + r * 256;
        int row = lin >> 3, f4 = lin & 7;
        uint32_t so = (uint32_t)((row * 8 + (f4 ^ (row & 7))) * 16);
        cp16(sb + so, A + (ll)(row0 + row) * lda + k0 + f4 * 8);
        cp16(sb + 16384 + so, Bg + (ll)(col0 + row) * ldb + k0 + f4 * 8);
    }
}

template <int BIAS, int EPI, bool STATS>
__global__ __launch_bounds__(256, 2)
void gemm_tn(const __half* __restrict__ A, ll sA, ll sA2, int lda,
             const __half* __restrict__ Bg, ll sB, ll sB2, int ldb,
             __half* __restrict__ Cm, ll sC, ll sC2, int ldc, int Kd,
             const float* __restrict__ bias, int biasStr,
             float scale, double* stS, double* stQ,
             float* lrow, ll sL) {
    extern __shared__ char smc[];
    const uint32_t smu = (uint32_t)__cvta_generic_to_shared(smc);
    const int bz = blockIdx.z, side = bz >> 4, b = bz & 15;
    A += (ll)b * sA + (ll)side * sA2;
    Bg += (ll)b * sB + (ll)side * sB2;
    Cm += (ll)b * sC + (ll)side * sC2;
    if (BIAS) bias += side * biasStr;
    if (EPI) lrow += (ll)bz * sL;
    const int row0 = blockIdx.y * 128, col0 = blockIdx.x * 128;
    const int tid = threadIdx.x, lane = tid & 31, warp = tid >> 5;
    const int wm = warp >> 2, wn = warp & 3;
    const int rA = lane & 15, selA = lane >> 4;
    const int tb = lane & 15, rB = tb & 7, midB = tb >> 3;

    float acc[4][4][4];
#pragma unroll
    for (int i = 0; i < 4; i++)
#pragma unroll
        for (int j = 0; j < 4; j++)
#pragma unroll
            for (int q = 0; q < 4; q++) acc[i][j][q] = 0.f;

    const int nT = Kd / 64;
    load_stage(smu, A, Bg, row0, col0, lda, ldb, 0, tid); cp_commit();
    load_stage(smu + 32768, A, Bg, row0, col0, lda, ldb, 64, tid); cp_commit();

    for (int t = 0; t < nT; t++) {
        if (t + 2 < nT)
            load_stage(smu + (uint32_t)(((t + 2) % 3) * 32768), A, Bg,
                       row0, col0, lda, ldb, (t + 2) * 64, tid);
        cp_commit();
        cp_wait<2>();
        __syncthreads();

        uint32_t Au = smu + (uint32_t)((t % 3) * 32768);
        uint32_t Bu = Au + 16384;
#pragma unroll
        for (int kt = 0; kt < 4; kt++) {
            uint32_t af[4][4], bf4[4][2];
#pragma unroll
            for (int mt = 0; mt < 4; mt++) {
                int row = wm * 64 + mt * 16 + rA;
                int u = kt * 2 + selA;
                ldsm_x4(af[mt], Au + (uint32_t)((row * 8 + (u ^ (row & 7))) * 16));
            }
#pragma unroll
            for (int nt = 0; nt < 4; nt++) {
                int row = wn * 32 + nt * 8 + rB;
                int u = kt * 2 + midB;
                ldsm_x2(bf4[nt], Bu + (uint32_t)((row * 8 + (u ^ (row & 7))) * 16));
            }
#pragma unroll
            for (int mt = 0; mt < 4; mt++)
#pragma unroll
                for (int nt = 0; nt < 4; nt++)
                    mma_f16(acc[mt][nt], af[mt], bf4[nt]);
        }
        __syncthreads();
    }

    const int gr = lane >> 2, gc = (lane & 3) * 2;
#pragma unroll
    for (int mt = 0; mt < 4; mt++) {
        int r0 = row0 + wm * 64 + mt * 16 + gr;
        float inv0 = 1.f, inv1 = 1.f;
        if (EPI == 2) { inv0 = 1.f / lrow[r0]; inv1 = 1.f / lrow[r0 + 8]; }
        float s0 = 0.f, q0 = 0.f, s1 = 0.f, q1 = 0.f;
#pragma unroll
        for (int nt = 0; nt < 4; nt++) {
            int col = col0 + wn * 32 + nt * 8 + gc;
            float v0x = acc[mt][nt][0] * scale, v0y = acc[mt][nt][1] * scale;
            float v1x = acc[mt][nt][2] * scale, v1y = acc[mt][nt][3] * scale;
            if (BIAS == 1) {
                float bx = bias[col], by = bias[col + 1];
                v0x += bx; v0y += by; v1x += bx; v1y += by;
            } else if (BIAS == 2) {
                float b0v = bias[r0], b1v = bias[r0 + 8];
                v0x += b0v; v0y += b0v; v1x += b1v; v1y += b1v;
            }
            if (EPI == 1) {
                __half2 h0 = __floats2half2_rn(v0x, v0y);
                __half2 h1 = __floats2half2_rn(v1x, v1y);
                uint32_t e0 = ex2_h2(*(uint32_t*)&h0);
                uint32_t e1 = ex2_h2(*(uint32_t*)&h1);
                float2 f0 = __half22float2(*(__half2*)&e0);
                float2 f1 = __half22float2(*(__half2*)&e1);
                s0 += f0.x + f0.y; s1 += f1.x + f1.y;
                *(uint32_t*)(Cm + (ll)r0 * ldc + col) = e0;
                *(uint32_t*)(Cm + (ll)(r0 + 8) * ldc + col) = e1;
                continue;
            }
            if (EPI == 2) { v0x *= inv0; v0y *= inv0; v1x *= inv1; v1y *= inv1; }
            if (STATS) {
                s0 += v0x + v0y; q0 += v0x * v0x + v0y * v0y;
                s1 += v1x + v1y; q1 += v1x * v1x + v1y * v1y;
            }
            *(__half2*)(Cm + (ll)r0 * ldc + col) = __floats2half2_rn(v0x, v0y);
            *(__half2*)(Cm + (ll)(r0 + 8) * ldc + col) = __floats2half2_rn(v1x, v1y);
        }
        if (EPI == 1) {
            s0 += __shfl_xor_sync(0xffffffffu, s0, 1); s0 += __shfl_xor_sync(0xffffffffu, s0, 2);
            s1 += __shfl_xor_sync(0xffffffffu, s1, 1); s1 += __shfl_xor_sync(0xffffffffu, s1, 2);
            if ((lane & 3) == 0) {
                atomicAdd(&lrow[r0], s0);
                atomicAdd(&lrow[r0 + 8], s1);
            }
        }
        if (STATS) {
            s0 += __shfl_xor_sync(0xffffffffu, s0, 1); s0 += __shfl_xor_sync(0xffffffffu, s0, 2);
            q0 += __shfl_xor_sync(0xffffffffu, q0, 1); q0 += __shfl_xor_sync(0xffffffffu, q0, 2);
            s1 += __shfl_xor_sync(0xffffffffu, s1, 1); s1 += __shfl_xor_sync(0xffffffffu, s1, 2);
            q1 += __shfl_xor_sync(0xffffffffu, q1, 1); q1 += __shfl_xor_sync(0xffffffffu, q1, 2);
            if ((lane & 3) == 0) {
                atomicAdd(&stS[r0], (double)s0);
                atomicAdd(&stQ[r0], (double)q0);
                atomicAdd(&stS[r0 + 8], (double)s1);
                atomicAdd(&stQ[r0 + 8], (double)q1);
            }
        }
    }
}

template <int BIAS, int EPI, bool STATS>
static void launch_tn(const __half* A, ll sA, ll sA2, int lda,
                      const __half* Bg, ll sB, ll sB2, int ldb,
                      __half* Cm, ll sC, ll sC2, int ldc,
                      int Md, int Nd, int Kd,
                      const float* bias, int biasStr,
                      float scale, int batch,
                      double* stS, double* stQ, float* lrow, ll sL) {
    cudaFuncSetAttribute(gemm_tn<BIAS, EPI, STATS>,
                         cudaFuncAttributeMaxDynamicSharedMemorySize, 98304);
    dim3 grid(Nd / 128, Md / 128, batch);
    gemm_tn<BIAS, EPI, STATS><<<grid, 256, 98304>>>(
        A, sA, sA2, lda, Bg, sB, sB2, ldb, Cm, sC, sC2, ldc, Kd,
        bias, biasStr, scale, stS, stQ, lrow, sL);
}

// ---------------- driver ----------------
extern "C" void kernel_launch(void* const* d_in, const int* in_sizes, int n_in,
                              void* d_out, int out_size) {
    const float* x = (const float*)d_in[0];
    int pb = (n_in > 1 && in_sizes[1] == 1) ? 2 : 1;
    const float* P[20];
    for (int i = 0; i < 20; i++) P[i] = (const float*)d_in[pb + i];
    float* out = (float*)d_out;

    __half *cat, *ctxh, *Qh, *Kh, *Vth, *Sh, *Ph, *Wh, *W3;
    float *bp, *bc, *lptr;
    double *stS, *stQ;
    cudaGetSymbolAddress((void**)&cat, g_cat);
    cudaGetSymbolAddress((void**)&ctxh, g_ctxh);
    cudaGetSymbolAddress((void**)&Qh, g_Qh);
    cudaGetSymbolAddress((void**)&Kh, g_Kh);
    cudaGetSymbolAddress((void**)&Vth, g_Vth);
    cudaGetSymbolAddress((void**)&Sh, g_Sh);
    cudaGetSymbolAddress((void**)&Ph, g_Ph);
    cudaGetSymbolAddress((void**)&Wh, g_Wh);
    cudaGetSymbolAddress((void**)&W3, g_W3);
    cudaGetSymbolAddress((void**)&bp, g_bp);
    cudaGetSymbolAddress((void**)&bc, g_bc);
    cudaGetSymbolAddress((void**)&lptr, g_l);
    cudaGetSymbolAddress((void**)&stS, g_sum);
    cudaGetSymbolAddress((void**)&stQ, g_sumsq);

    const int CC = C_ * C_;
    const float LOG2E = 1.4426950408889634f;

    pack_w<<<1536, 256>>>(P[0], P[8], P[2], P[10], P[4], P[12],
                          P[1], P[9], P[3], P[11], P[5], P[13]);  // + zero init
    transpose_kernel<<<dim3(N_ / 32, C_ / 32, B_), dim3(32, 8)>>>(x);
    score2_kernel<<<dim3(N_ / 8, B_), 256>>>();
    select_kernel<<<dim3(B_, 2), 1024>>>();
    gather_kernel<<<dim3(M_ / 8, B_, 2), 256>>>();
    combine_w<<<256, 256>>>(P[16], P[6], P[14], P[17], P[7], P[15]);

    // Q (both sides)
    launch_tn<1, 0, false>(cat + 512, (ll)N_ * 768, 0, 768,
                           Wh, 0, 0, C_,
                           Qh, (ll)N_ * 512, 0, 512,
                           N_, 512, C_, bp, 0, 1.f, B_, nullptr, nullptr, nullptr, 0);
    // K
    launch_tn<1, 0, false>(ctxh, (ll)M_ * C_, (ll)B_ * M_ * C_, C_,
                           Wh + 2 * CC, 0, CC, C_,
                           Kh, (ll)M_ * C_, (ll)B_ * M_ * C_, C_,
                           M_, C_, C_, bp + 512, 256, 1.f, 2 * B_, nullptr, nullptr, nullptr, 0);
    // V^T
    launch_tn<2, 0, false>(Wh + 4 * CC, 0, CC, C_,
                           ctxh, (ll)M_ * C_, (ll)B_ * M_ * C_, C_,
                           Vth, (ll)C_ * M_, (ll)B_ * C_ * M_, M_,
                           C_, M_, C_, bp + 1024, 256, 1.f, 2 * B_, nullptr, nullptr, nullptr, 0);
    // S~ = 2^(Q·K^T * log2e/16), row sums
    launch_tn<0, 1, false>(Qh, (ll)N_ * 512, (ll)C_, 512,
                           Kh, (ll)M_ * C_, (ll)B_ * M_ * C_, C_,
                           Sh, (ll)N_ * M_, (ll)B_ * N_ * M_, M_,
                           N_, M_, C_, nullptr, 0, LOG2E / 16.f, 2 * B_,
                           nullptr, nullptr, lptr, N_);
    // Y = (S~·V)/l -> cat slots
    launch_tn<0, 2, false>(Sh, (ll)N_ * M_, (ll)B_ * N_ * M_, M_,
                           Vth, (ll)C_ * M_, (ll)B_ * C_ * M_, M_,
                           cat, (ll)N_ * 768, 256, 768,
                           N_, C_, M_, nullptr, 0, 1.f, 2 * B_,
                           nullptr, nullptr, lptr, N_);
    // fuse + BN stats
    launch_tn<2, 0, true>(W3, 0, 0, 768,
                          cat, (ll)N_ * 768, 0, 768,
                          Ph, (ll)C_ * N_, 0, N_,
                          C_, N_, 768, bc, 0, 1.f, B_, stS, stQ, nullptr, 0);

    bn_final<<<dim3(N_ / 1024, C_, B_), 256>>>(out, P[18], P[19]);
}

// round 15
// speedup vs baseline: 1.0358x; 1.0358x over previous
#include <cuda_runtime.h>
#include <cuda_fp16.h>
#include <cstdint>

#define B_ 16
#define C_ 256
#define N_ 4096
#define M_ 1024
#define EPS_ 1e-5f
typedef long long ll;

// ---------------- scratch ----------------
__device__ float g_xm[B_ * C_];
__device__ float g_score[B_ * N_];       // pass1: ||x_n||^2 ; pass2: monotone uint key
__device__ int   g_idx[2 * B_ * M_];
__device__ double g_sum[C_];
__device__ double g_sumsq[C_];
__device__ float g_bnw[C_];
__device__ float g_bnb[C_];
__device__ float g_bp[3 * 512];          // packed biases: bq2|bk2|bv2
__device__ float g_bc[C_];               // bconst for final gemm
__device__ float g_l[2 * B_ * N_];       // softmax row sums

__device__ __half g_cat[(ll)B_ * N_ * 768];   // [b][n][ Y_s(256) | Y_g(256) | x(256) ]
__device__ __half g_ctxh[2LL * B_ * M_ * C_]; // [side][b][m][c]
__device__ __half g_Qh[(ll)B_ * N_ * 512];    // [b][n][512]
__device__ __half g_Kh[2LL * B_ * M_ * C_];
__device__ __half g_Vth[2LL * B_ * C_ * M_];  // [side][b][d][m]
__device__ __half g_Sh[2LL * B_ * N_ * M_];   // unnormalized exp scores
__device__ __half g_Ph[(ll)B_ * C_ * N_];     // pre-BN output
__device__ __half g_Wh[6 * C_ * C_];          // Wq_s,Wq_g,Wk_s,Wk_g,Wv_s,Wv_g
__device__ __half g_W3[C_ * 768];             // [Wc_s | Wc_g | Wx]

// ---------------- PTX ----------------
__device__ __forceinline__ void cp16(uint32_t dst, const void* src) {
    asm volatile("cp.async.cg.shared.global [%0], [%1], 16;" :: "r"(dst), "l"(src));
}
__device__ __forceinline__ void cp_commit() { asm volatile("cp.async.commit_group;"); }
template <int Nw> __device__ __forceinline__ void cp_wait() {
    asm volatile("cp.async.wait_group %0;" :: "n"(Nw));
}
__device__ __forceinline__ void ldsm_x4(uint32_t* r, uint32_t a) {
    asm volatile("ldmatrix.sync.aligned.m8n8.x4.shared.b16 {%0,%1,%2,%3}, [%4];"
        : "=r"(r[0]), "=r"(r[1]), "=r"(r[2]), "=r"(r[3]) : "r"(a));
}
__device__ __forceinline__ void ldsm_x2(uint32_t* r, uint32_t a) {
    asm volatile("ldmatrix.sync.aligned.m8n8.x2.shared.b16 {%0,%1}, [%2];"
        : "=r"(r[0]), "=r"(r[1]) : "r"(a));
}
__device__ __forceinline__ void mma_f16(float* c, const uint32_t* a, const uint32_t* b) {
    asm volatile("mma.sync.aligned.m16n8k16.row.col.f32.f16.f16.f32 "
        "{%0,%1,%2,%3}, {%4,%5,%6,%7}, {%8,%9}, {%0,%1,%2,%3};"
        : "+f"(c[0]), "+f"(c[1]), "+f"(c[2]), "+f"(c[3])
        : "r"(a[0]), "r"(a[1]), "r"(a[2]), "r"(a[3]), "r"(b[0]), "r"(b[1]));
}
__device__ __forceinline__ uint32_t ex2_h2(uint32_t u) {
    asm("ex2.approx.f16x2 %0, %0;" : "+r"(u));
    return u;
}

// ---------------- small kernels ----------------
// transpose fp32 [b][c][n] -> fp16 cat x-slot; fused mean + per-point sumsq accumulation
__global__ void transpose_kernel(const float* __restrict__ x) {
    __shared__ float t[32][33];
    __shared__ float ps[32][9];
    __shared__ float ps2[32][9];
    int b = blockIdx.z, n0 = blockIdx.x * 32, c0 = blockIdx.y * 32;
    int tx = threadIdx.x, ty = threadIdx.y;  // (32, 8)
    const float* xp = x + (ll)b * C_ * N_;
    __half* xhp = g_cat + (ll)b * N_ * 768 + 512;
#pragma unroll
    for (int i = 0; i < 32; i += 8)
        t[ty + i][tx] = xp[(ll)(c0 + ty + i) * N_ + n0 + tx];
    __syncthreads();
#pragma unroll
    for (int i = 0; i < 32; i += 8)
        xhp[(ll)(n0 + ty + i) * 768 + c0 + tx] = __float2half_rn(t[tx][ty + i]);
    float s = 0.f;
#pragma unroll
    for (int q = 0; q < 4; q++) s += t[tx][ty * 4 + q];
    ps[tx][ty] = s;
    float s2 = 0.f;
#pragma unroll
    for (int q = 0; q < 4; q++) { float v = t[ty * 4 + q][tx]; s2 += v * v; }
    ps2[tx][ty] = s2;
    __syncthreads();
    if (ty == 0) {
        float tot = 0.f, tot2 = 0.f;
#pragma unroll
        for (int q = 0; q < 8; q++) { tot += ps[tx][q]; tot2 += ps2[tx][q]; }
        atomicAdd(&g_xm[b * C_ + c0 + tx], tot * (1.0f / N_));
        atomicAdd(&g_score[b * N_ + n0 + tx], tot2);
    }
}

// full-grid scoring: warp-per-point over fp16 x; writes monotone uint key in place
__global__ void score2_kernel() {
    int b = blockIdx.y;
    int warp = threadIdx.x >> 5, lane = threadIdx.x & 31;
    int n = blockIdx.x * 8 + warp;
    float mr[8];
    {
        const float4* mp = (const float4*)(g_xm + b * C_);
        float4 m0 = mp[lane * 2], m1 = mp[lane * 2 + 1];
        mr[0] = m0.x; mr[1] = m0.y; mr[2] = m0.z; mr[3] = m0.w;
        mr[4] = m1.x; mr[5] = m1.y; mr[6] = m1.z; mr[7] = m1.w;
    }
    uint4 v = ((const uint4*)(g_cat + ((ll)b * N_ + n) * 768 + 512))[lane];
    float2 f0 = __half22float2(*(__half2*)&v.x);
    float2 f1 = __half22float2(*(__half2*)&v.y);
    float2 f2 = __half22float2(*(__half2*)&v.z);
    float2 f3 = __half22float2(*(__half2*)&v.w);
    float dot = f0.x * mr[0] + f0.y * mr[1] + f1.x * mr[2] + f1.y * mr[3]
              + f2.x * mr[4] + f2.y * mr[5] + f3.x * mr[6] + f3.y * mr[7];
#pragma unroll
    for (int o = 16; o; o >>= 1) dot += __shfl_xor_sync(0xffffffffu, dot, o);
    if (lane == 0) {
        float sc = g_score[b * N_ + n] - 2.f * dot;  // + ||mu||^2 const dropped
        uint32_t u = __float_as_uint(sc);
        u ^= (uint32_t)(((int)u >> 31)) | 0x80000000u;  // monotone float->uint
        ((uint32_t*)g_score)[b * N_ + n] = u;
    }
}

// radix-select: one block per (batch, direction); warp-shfl scan (2 barriers/pass)
__global__ void select_kernel() {
    __shared__ uint32_t sv[N_];
    __shared__ int hist[256];
    __shared__ int wtot[8], woff[8];
    __shared__ int s_digit, s_k, s_cnt, s_base, s_total;
    int b = blockIdx.x, dir = blockIdx.y, t = threadIdx.x;  // 1024 threads
    int lane = t & 31, wid = t >> 5;
    for (int i = t; i < N_; i += 1024) sv[i] = ((const uint32_t*)g_score)[b * N_ + i];
    __syncthreads();

    uint32_t prefix = 0, pmask = 0;
    int k = M_;
    for (int pass = 0; pass < 4; pass++) {
        int shift = 24 - 8 * pass;
        if (t < 256) hist[t] = 0;
        __syncthreads();
        for (int i = t; i < N_; i += 1024) {
            uint32_t v = sv[i];
            if ((v & pmask) == prefix) atomicAdd(&hist[(v >> shift) & 255], 1);
        }
        __syncthreads();
        int val = 0, h = 0;
        if (t < 256) {
            h = hist[t]; val = h;
#pragma unroll
            for (int off = 1; off < 32; off <<= 1) {
                int nv = __shfl_up_sync(0xffffffffu, val, off);
                if (lane >= off) val += nv;
            }
            if (lane == 31) wtot[wid] = val;
        }
        __syncthreads();
        if (t == 0) {
            int acc = 0;
#pragma unroll
            for (int w = 0; w < 8; w++) { woff[w] = acc; acc += wtot[w]; }
            s_total = acc;
        }
        __syncthreads();
        if (t < 256) {
            int incl = val + woff[wid];
            int excl = incl - h;
            int total = s_total;
            if (dir == 0) {
                int above = total - incl, atLeast = total - excl;
                if (atLeast >= k && above < k) { s_digit = t; s_k = k - above; }
            } else {
                if (incl >= k && excl < k) { s_digit = t; s_k = k - excl; }
            }
        }
        __syncthreads();
        prefix |= ((uint32_t)s_digit) << shift;
        pmask |= 0xFFu << shift;
        k = s_k;
        __syncthreads();
    }
    uint32_t T = prefix;
    int keq = k;
    if (t == 0) s_cnt = 0;
    __syncthreads();
    int* dst = g_idx + dir * B_ * M_ + b * M_;
    for (int i = t; i < N_; i += 1024) {
        uint32_t v = sv[i];
        bool strict = (dir == 0) ? (v > T) : (v < T);
        if (strict) dst[atomicAdd(&s_cnt, 1)] = i;
    }
    __syncthreads();
    if (t == 0) { s_base = s_cnt; s_cnt = 0; }
    __syncthreads();
    for (int i = t; i < N_; i += 1024) {
        if (sv[i] == T) {
            int e = atomicAdd(&s_cnt, 1);
            if (e < keq) dst[s_base + e] = i;
        }
    }
}

__global__ void gather_kernel() {
    int side = blockIdx.z, b = blockIdx.y;
    int m = blockIdx.x * 8 + (threadIdx.x >> 5);
    int c8 = threadIdx.x & 31;
    int j = g_idx[side * B_ * M_ + b * M_ + m];
    uint4 v = ((const uint4*)(g_cat + ((ll)b * N_ + j) * 768 + 512))[c8];
    ((uint4*)(g_ctxh + (((ll)side * B_ + b) * M_ + m) * C_))[c8] = v;
}

// pack_w: weights->fp16, biases->g_bp, zero-init l/xm/score/stats
__global__ void pack_w(const float* a0, const float* a1, const float* a2,
                       const float* a3, const float* a4, const float* a5,
                       const float* b0, const float* b1, const float* b2,
                       const float* b3, const float* b4, const float* b5) {
    int i = blockIdx.x * 256 + threadIdx.x;  // 393216 threads
    const float* p[6] = {a0, a1, a2, a3, a4, a5};
    g_Wh[i] = __float2half_rn(p[i >> 16][i & 65535]);
    if (i < 2 * B_ * N_) g_l[i] = 0.f;
    if (i < B_ * N_) g_score[i] = 0.f;
    if (i < B_ * C_) g_xm[i] = 0.f;
    if (i < C_) { g_sum[i] = 0.0; g_sumsq[i] = 0.0; }
    if (i < 1536) {
        const float* q[6] = {b0, b1, b2, b3, b4, b5};
        int grp = i >> 9, k = i & 511;
        g_bp[i] = q[(grp << 1) | (k >> 8)][k & 255];
    }
}

__global__ void combine_w(const float* __restrict__ Wf,
                          const float* __restrict__ Wo_s, const float* __restrict__ Wo_g,
                          const float* __restrict__ bf,
                          const float* __restrict__ bo_s, const float* __restrict__ bo_g) {
    int d = blockIdx.x, t = threadIdx.x;
    __shared__ float wf[512];
    wf[t] = Wf[d * 512 + t];
    wf[t + 256] = Wf[d * 512 + 256 + t];
    __syncthreads();
    float a0 = 0.f, a1 = 0.f;
#pragma unroll 4
    for (int e = 0; e < 256; e++) {
        a0 += wf[e] * Wo_s[e * 256 + t];
        a1 += wf[256 + e] * Wo_g[e * 256 + t];
    }
    g_W3[d * 768 + t] = __float2half_rn(a0);
    g_W3[d * 768 + 256 + t] = __float2half_rn(a1);
    g_W3[d * 768 + 512 + t] = __float2half_rn(wf[t] + wf[256 + t]);
    if (t == 0) {
        float bc = bf[d];
        for (int e = 0; e < 256; e++) bc += wf[e] * bo_s[e] + wf[256 + e] * bo_g[e];
        g_bc[d] = bc;
    }
}

__global__ void bn_finalize(const float* __restrict__ gamma, const float* __restrict__ beta) {
    int d = threadIdx.x;  // 256
    double cnt = (double)B_ * N_;
    double mu = g_sum[d] / cnt;
    double var = g_sumsq[d] / cnt - mu * mu;
    float w = gamma[d] * rsqrtf((float)var + EPS_);
    g_bnw[d] = w;
    g_bnb[d] = beta[d] - (float)mu * w;
}

__global__ void bn_final(float* __restrict__ out) {
    int i = blockIdx.x * 256 + threadIdx.x;  // N/4 per (d,b)
    int d = blockIdx.y, b = blockIdx.z;
    ll base = ((ll)b * C_ + d) * N_;
    uint2 raw = ((const uint2*)(g_Ph + base))[i];
    float2 f0 = __half22float2(*(__half2*)&raw.x);
    float2 f1 = __half22float2(*(__half2*)&raw.y);
    float w = g_bnw[d], bb = g_bnb[d];
    float4 o;
    o.x = fmaxf(f0.x * w + bb, 0.f);
    o.y = fmaxf(f0.y * w + bb, 0.f);
    o.z = fmaxf(f1.x * w + bb, 0.f);
    o.w = fmaxf(f1.y * w + bb, 0.f);
    ((float4*)(out + base))[i] = o;
}

// ---------------- fp16 TN GEMM: 3-stage cp.async pipeline ----------------
// EPI: 0 none, 1 ex2(h2)+rowsum (scale pre-folds log2e), 2 div-by-l
__device__ __forceinline__ void load_stage(uint32_t sb, const __half* A, const __half* Bg,
                                           int row0, int col0, int lda, int ldb,
                                           int k0, int tid) {
#pragma unroll
    for (int r = 0; r < 4; r++) {
        int lin = tid + r * 256;
        int row = lin >> 3, f4 = lin & 7;
        uint32_t so = (uint32_t)((row * 8 + (f4 ^ (row & 7))) * 16);
        cp16(sb + so, A + (ll)(row0 + row) * lda + k0 + f4 * 8);
        cp16(sb + 16384 + so, Bg + (ll)(col0 + row) * ldb + k0 + f4 * 8);
    }
}

template <int BIAS, int EPI, bool STATS>
__global__ __launch_bounds__(256, 2)
void gemm_tn(const __half* __restrict__ A, ll sA, ll sA2, int lda,
             const __half* __restrict__ Bg, ll sB, ll sB2, int ldb,
             __half* __restrict__ Cm, ll sC, ll sC2, int ldc, int Kd,
             const float* __restrict__ bias, int biasStr,
             float scale, double* stS, double* stQ,
             float* lrow, ll sL) {
    extern __shared__ char smc[];
    const uint32_t smu = (uint32_t)__cvta_generic_to_shared(smc);
    const int bz = blockIdx.z, side = bz >> 4, b = bz & 15;
    A += (ll)b * sA + (ll)side * sA2;
    Bg += (ll)b * sB + (ll)side * sB2;
    Cm += (ll)b * sC + (ll)side * sC2;
    if (BIAS) bias += side * biasStr;
    if (EPI) lrow += (ll)bz * sL;
    const int row0 = blockIdx.y * 128, col0 = blockIdx.x * 128;
    const int tid = threadIdx.x, lane = tid & 31, warp = tid >> 5;
    const int wm = warp >> 2, wn = warp & 3;
    const int rA = lane & 15, selA = lane >> 4;
    const int tb = lane & 15, rB = tb & 7, midB = tb >> 3;

    float acc[4][4][4];
#pragma unroll
    for (int i = 0; i < 4; i++)
#pragma unroll
        for (int j = 0; j < 4; j++)
#pragma unroll
            for (int q = 0; q < 4; q++) acc[i][j][q] = 0.f;

    const int nT = Kd / 64;
    load_stage(smu, A, Bg, row0, col0, lda, ldb, 0, tid); cp_commit();
    load_stage(smu + 32768, A, Bg, row0, col0, lda, ldb, 64, tid); cp_commit();

    for (int t = 0; t < nT; t++) {
        if (t + 2 < nT)
            load_stage(smu + (uint32_t)(((t + 2) % 3) * 32768), A, Bg,
                       row0, col0, lda, ldb, (t + 2) * 64, tid);
        cp_commit();
        cp_wait<2>();
        __syncthreads();

        uint32_t Au = smu + (uint32_t)((t % 3) * 32768);
        uint32_t Bu = Au + 16384;
#pragma unroll
        for (int kt = 0; kt < 4; kt++) {
            uint32_t af[4][4], bf4[4][2];
#pragma unroll
            for (int mt = 0; mt < 4; mt++) {
                int row = wm * 64 + mt * 16 + rA;
                int u = kt * 2 + selA;
                ldsm_x4(af[mt], Au + (uint32_t)((row * 8 + (u ^ (row & 7))) * 16));
            }
#pragma unroll
            for (int nt = 0; nt < 4; nt++) {
                int row = wn * 32 + nt * 8 + rB;
                int u = kt * 2 + midB;
                ldsm_x2(bf4[nt], Bu + (uint32_t)((row * 8 + (u ^ (row & 7))) * 16));
            }
#pragma unroll
            for (int mt = 0; mt < 4; mt++)
#pragma unroll
                for (int nt = 0; nt < 4; nt++)
                    mma_f16(acc[mt][nt], af[mt], bf4[nt]);
        }
        __syncthreads();
    }

    const int gr = lane >> 2, gc = (lane & 3) * 2;
#pragma unroll
    for (int mt = 0; mt < 4; mt++) {
        int r0 = row0 + wm * 64 + mt * 16 + gr;
        float inv0 = 1.f, inv1 = 1.f;
        if (EPI == 2) { inv0 = 1.f / lrow[r0]; inv1 = 1.f / lrow[r0 + 8]; }
        float s0 = 0.f, q0 = 0.f, s1 = 0.f, q1 = 0.f;
#pragma unroll
        for (int nt = 0; nt < 4; nt++) {
            int col = col0 + wn * 32 + nt * 8 + gc;
            float v0x = acc[mt][nt][0] * scale, v0y = acc[mt][nt][1] * scale;
            float v1x = acc[mt][nt][2] * scale, v1y = acc[mt][nt][3] * scale;
            if (BIAS == 1) {
                float bx = bias[col], by = bias[col + 1];
                v0x += bx; v0y += by; v1x += bx; v1y += by;
            } else if (BIAS == 2) {
                float b0v = bias[r0], b1v = bias[r0 + 8];
                v0x += b0v; v0y += b0v; v1x += b1v; v1y += b1v;
            }
            if (EPI == 1) {
                __half2 h0 = __floats2half2_rn(v0x, v0y);
                __half2 h1 = __floats2half2_rn(v1x, v1y);
                uint32_t e0 = ex2_h2(*(uint32_t*)&h0);
                uint32_t e1 = ex2_h2(*(uint32_t*)&h1);
                float2 f0 = __half22float2(*(__half2*)&e0);
                float2 f1 = __half22float2(*(__half2*)&e1);
                s0 += f0.x + f0.y; s1 += f1.x + f1.y;
                *(uint32_t*)(Cm + (ll)r0 * ldc + col) = e0;
                *(uint32_t*)(Cm + (ll)(r0 + 8) * ldc + col) = e1;
                continue;
            }
            if (EPI == 2) { v0x *= inv0; v0y *= inv0; v1x *= inv1; v1y *= inv1; }
            if (STATS) {
                s0 += v0x + v0y; q0 += v0x * v0x + v0y * v0y;
                s1 += v1x + v1y; q1 += v1x * v1x + v1y * v1y;
            }
            *(__half2*)(Cm + (ll)r0 * ldc + col) = __floats2half2_rn(v0x, v0y);
            *(__half2*)(Cm + (ll)(r0 + 8) * ldc + col) = __floats2half2_rn(v1x, v1y);
        }
        if (EPI == 1) {
            s0 += __shfl_xor_sync(0xffffffffu, s0, 1); s0 += __shfl_xor_sync(0xffffffffu, s0, 2);
            s1 += __shfl_xor_sync(0xffffffffu, s1, 1); s1 += __shfl_xor_sync(0xffffffffu, s1, 2);
            if ((lane & 3) == 0) {
                atomicAdd(&lrow[r0], s0);
                atomicAdd(&lrow[r0 + 8], s1);
            }
        }
        if (STATS) {
            s0 += __shfl_xor_sync(0xffffffffu, s0, 1); s0 += __shfl_xor_sync(0xffffffffu, s0, 2);
            q0 += __shfl_xor_sync(0xffffffffu, q0, 1); q0 += __shfl_xor_sync(0xffffffffu, q0, 2);
            s1 += __shfl_xor_sync(0xffffffffu, s1, 1); s1 += __shfl_xor_sync(0xffffffffu, s1, 2);
            q1 += __shfl_xor_sync(0xffffffffu, q1, 1); q1 += __shfl_xor_sync(0xffffffffu, q1, 2);
            if ((lane & 3) == 0) {
                atomicAdd(&stS[r0], (double)s0);
                atomicAdd(&stQ[r0], (double)q0);
                atomicAdd(&stS[r0 + 8], (double)s1);
                atomicAdd(&stQ[r0 + 8], (double)q1);
            }
        }
    }
}

template <int BIAS, int EPI, bool STATS>
static void launch_tn(const __half* A, ll sA, ll sA2, int lda,
                      const __half* Bg, ll sB, ll sB2, int ldb,
                      __half* Cm, ll sC, ll sC2, int ldc,
                      int Md, int Nd, int Kd,
                      const float* bias, int biasStr,
                      float scale, int batch,
                      double* stS, double* stQ, float* lrow, ll sL) {
    cudaFuncSetAttribute(gemm_tn<BIAS, EPI, STATS>,
                         cudaFuncAttributeMaxDynamicSharedMemorySize, 98304);
    dim3 grid(Nd / 128, Md / 128, batch);
    gemm_tn<BIAS, EPI, STATS><<<grid, 256, 98304>>>(
        A, sA, sA2, lda, Bg, sB, sB2, ldb, Cm, sC, sC2, ldc, Kd,
        bias, biasStr, scale, stS, stQ, lrow, sL);
}

// ---------------- driver ----------------
extern "C" void kernel_launch(void* const* d_in, const int* in_sizes, int n_in,
                              void* d_out, int out_size) {
    const float* x = (const float*)d_in[0];
    int pb = (n_in > 1 && in_sizes[1] == 1) ? 2 : 1;
    const float* P[20];
    for (int i = 0; i < 20; i++) P[i] = (const float*)d_in[pb + i];
    float* out = (float*)d_out;

    __half *cat, *ctxh, *Qh, *Kh, *Vth, *Sh, *Ph, *Wh, *W3;
    float *bp, *bc, *lptr;
    double *stS, *stQ;
    cudaGetSymbolAddress((void**)&cat, g_cat);
    cudaGetSymbolAddress((void**)&ctxh, g_ctxh);
    cudaGetSymbolAddress((void**)&Qh, g_Qh);
    cudaGetSymbolAddress((void**)&Kh, g_Kh);
    cudaGetSymbolAddress((void**)&Vth, g_Vth);
    cudaGetSymbolAddress((void**)&Sh, g_Sh);
    cudaGetSymbolAddress((void**)&Ph, g_Ph);
    cudaGetSymbolAddress((void**)&Wh, g_Wh);
    cudaGetSymbolAddress((void**)&W3, g_W3);
    cudaGetSymbolAddress((void**)&bp, g_bp);
    cudaGetSymbolAddress((void**)&bc, g_bc);
    cudaGetSymbolAddress((void**)&lptr, g_l);
    cudaGetSymbolAddress((void**)&stS, g_sum);
    cudaGetSymbolAddress((void**)&stQ, g_sumsq);

    const int CC = C_ * C_;
    const float LOG2E = 1.4426950408889634f;

    pack_w<<<1536, 256>>>(P[0], P[8], P[2], P[10], P[4], P[12],
                          P[1], P[9], P[3], P[11], P[5], P[13]);  // + zero init
    transpose_kernel<<<dim3(N_ / 32, C_ / 32, B_), dim3(32, 8)>>>(x);
    score2_kernel<<<dim3(N_ / 8, B_), 256>>>();
    select_kernel<<<dim3(B_, 2), 1024>>>();
    gather_kernel<<<dim3(M_ / 8, B_, 2), 256>>>();
    combine_w<<<256, 256>>>(P[16], P[6], P[14], P[17], P[7], P[15]);

    // Q (both sides)
    launch_tn<1, 0, false>(cat + 512, (ll)N_ * 768, 0, 768,
                           Wh, 0, 0, C_,
                           Qh, (ll)N_ * 512, 0, 512,
                           N_, 512, C_, bp, 0, 1.f, B_, nullptr, nullptr, nullptr, 0);
    // K
    launch_tn<1, 0, false>(ctxh, (ll)M_ * C_, (ll)B_ * M_ * C_, C_,
                           Wh + 2 * CC, 0, CC, C_,
                           Kh, (ll)M_ * C_, (ll)B_ * M_ * C_, C_,
                           M_, C_, C_, bp + 512, 256, 1.f, 2 * B_, nullptr, nullptr, nullptr, 0);
    // V^T
    launch_tn<2, 0, false>(Wh + 4 * CC, 0, CC, C_,
                           ctxh, (ll)M_ * C_, (ll)B_ * M_ * C_, C_,
                           Vth, (ll)C_ * M_, (ll)B_ * C_ * M_, M_,
                           C_, M_, C_, bp + 1024, 256, 1.f, 2 * B_, nullptr, nullptr, nullptr, 0);
    // S~ = 2^(Q·K^T * log2e/16), row sums
    launch_tn<0, 1, false>(Qh, (ll)N_ * 512, (ll)C_, 512,
                           Kh, (ll)M_ * C_, (ll)B_ * M_ * C_, C_,
                           Sh, (ll)N_ * M_, (ll)B_ * N_ * M_, M_,
                           N_, M_, C_, nullptr, 0, LOG2E / 16.f, 2 * B_,
                           nullptr, nullptr, lptr, N_);
    // Y = (S~·V)/l -> cat slots
    launch_tn<0, 2, false>(Sh, (ll)N_ * M_, (ll)B_ * N_ * M_, M_,
                           Vth, (ll)C_ * M_, (ll)B_ * C_ * M_, M_,
                           cat, (ll)N_ * 768, 256, 768,
                           N_, C_, M_, nullptr, 0, 1.f, 2 * B_,
                           nullptr, nullptr, lptr, N_);
    // fuse + BN stats
    launch_tn<2, 0, true>(W3, 0, 0, 768,
                          cat, (ll)N_ * 768, 0, 768,
                          Ph, (ll)C_ * N_, 0, N_,
                          C_, N_, 768, bc, 0, 1.f, B_, stS, stQ, nullptr, 0);

    bn_finalize<<<1, 256>>>(P[18], P[19]);
    bn_final<<<dim3(N_ / 1024, C_, B_), 256>>>(out);
}

// round 16
// speedup vs baseline: 1.0866x; 1.0490x over previous
#include <cuda_runtime.h>
#include <cuda_fp16.h>
#include <cstdint>

#define B_ 16
#define C_ 256
#define N_ 4096
#define M_ 1024
#define EPS_ 1e-5f
typedef long long ll;

// ---------------- scratch ----------------
__device__ float g_xm[B_ * C_];
__device__ float g_score[B_ * N_];       // pass1: ||x_n||^2 ; pass2: monotone uint key
__device__ int   g_idx[2 * B_ * M_];
__device__ double g_sum[C_];
__device__ double g_sumsq[C_];
__device__ float g_bnw[C_];
__device__ float g_bnb[C_];
__device__ float g_bp[3 * 512];          // packed biases: bq2|bk2|bv2
__device__ float g_bc[C_];               // bconst for final gemm
__device__ float g_bqk[2 * B_ * M_];     // per-(side,b) S-column bias: (K·bq)*log2e/16
__device__ float g_l[2 * B_ * N_];       // softmax row sums

__device__ __half g_cat[(ll)B_ * N_ * 768];   // [b][n][ Y_s(256) | Y_g(256) | x(256) ]
__device__ __half g_ctxh[2LL * B_ * M_ * C_]; // [side][b][m][c]
__device__ __half g_K2h[2LL * B_ * M_ * C_];  // K'' = K·Wq  [side][b][m][c]
__device__ __half g_Kh[2LL * B_ * M_ * C_];
__device__ __half g_Vth[2LL * B_ * C_ * M_];  // [side][b][d][m]
__device__ __half g_Sh[2LL * B_ * N_ * M_];   // unnormalized exp scores
__device__ __half g_Ph[(ll)B_ * C_ * N_];     // pre-BN output
__device__ __half g_Wh[6 * C_ * C_];          // WqT_s,WqT_g,Wk_s,Wk_g,Wv_s,Wv_g
__device__ __half g_W3[C_ * 768];             // [Wc_s | Wc_g | Wx]

// ---------------- PTX ----------------
__device__ __forceinline__ void cp16(uint32_t dst, const void* src) {
    asm volatile("cp.async.cg.shared.global [%0], [%1], 16;" :: "r"(dst), "l"(src));
}
__device__ __forceinline__ void cp_commit() { asm volatile("cp.async.commit_group;"); }
template <int Nw> __device__ __forceinline__ void cp_wait() {
    asm volatile("cp.async.wait_group %0;" :: "n"(Nw));
}
__device__ __forceinline__ void ldsm_x4(uint32_t* r, uint32_t a) {
    asm volatile("ldmatrix.sync.aligned.m8n8.x4.shared.b16 {%0,%1,%2,%3}, [%4];"
        : "=r"(r[0]), "=r"(r[1]), "=r"(r[2]), "=r"(r[3]) : "r"(a));
}
__device__ __forceinline__ void ldsm_x2(uint32_t* r, uint32_t a) {
    asm volatile("ldmatrix.sync.aligned.m8n8.x2.shared.b16 {%0,%1}, [%2];"
        : "=r"(r[0]), "=r"(r[1]) : "r"(a));
}
__device__ __forceinline__ void mma_f16(float* c, const uint32_t* a, const uint32_t* b) {
    asm volatile("mma.sync.aligned.m16n8k16.row.col.f32.f16.f16.f32 "
        "{%0,%1,%2,%3}, {%4,%5,%6,%7}, {%8,%9}, {%0,%1,%2,%3};"
        : "+f"(c[0]), "+f"(c[1]), "+f"(c[2]), "+f"(c[3])
        : "r"(a[0]), "r"(a[1]), "r"(a[2]), "r"(a[3]), "r"(b[0]), "r"(b[1]));
}
__device__ __forceinline__ uint32_t ex2_h2(uint32_t u) {
    asm("ex2.approx.f16x2 %0, %0;" : "+r"(u));
    return u;
}

// ---------------- small kernels ----------------
// transpose fp32 [b][c][n] -> fp16 cat x-slot; fused mean + per-point sumsq accumulation
__global__ void transpose_kernel(const float* __restrict__ x) {
    __shared__ float t[32][33];
    __shared__ float ps[32][9];
    __shared__ float ps2[32][9];
    int b = blockIdx.z, n0 = blockIdx.x * 32, c0 = blockIdx.y * 32;
    int tx = threadIdx.x, ty = threadIdx.y;  // (32, 8)
    const float* xp = x + (ll)b * C_ * N_;
    __half* xhp = g_cat + (ll)b * N_ * 768 + 512;
#pragma unroll
    for (int i = 0; i < 32; i += 8)
        t[ty + i][tx] = xp[(ll)(c0 + ty + i) * N_ + n0 + tx];
    __syncthreads();
#pragma unroll
    for (int i = 0; i < 32; i += 8)
        xhp[(ll)(n0 + ty + i) * 768 + c0 + tx] = __float2half_rn(t[tx][ty + i]);
    float s = 0.f;
#pragma unroll
    for (int q = 0; q < 4; q++) s += t[tx][ty * 4 + q];
    ps[tx][ty] = s;
    float s2 = 0.f;
#pragma unroll
    for (int q = 0; q < 4; q++) { float v = t[ty * 4 + q][tx]; s2 += v * v; }
    ps2[tx][ty] = s2;
    __syncthreads();
    if (ty == 0) {
        float tot = 0.f, tot2 = 0.f;
#pragma unroll
        for (int q = 0; q < 8; q++) { tot += ps[tx][q]; tot2 += ps2[tx][q]; }
        atomicAdd(&g_xm[b * C_ + c0 + tx], tot * (1.0f / N_));
        atomicAdd(&g_score[b * N_ + n0 + tx], tot2);
    }
}

// full-grid scoring: warp-per-point over fp16 x; writes monotone uint key in place
__global__ void score2_kernel() {
    int b = blockIdx.y;
    int warp = threadIdx.x >> 5, lane = threadIdx.x & 31;
    int n = blockIdx.x * 8 + warp;
    float mr[8];
    {
        const float4* mp = (const float4*)(g_xm + b * C_);
        float4 m0 = mp[lane * 2], m1 = mp[lane * 2 + 1];
        mr[0] = m0.x; mr[1] = m0.y; mr[2] = m0.z; mr[3] = m0.w;
        mr[4] = m1.x; mr[5] = m1.y; mr[6] = m1.z; mr[7] = m1.w;
    }
    uint4 v = ((const uint4*)(g_cat + ((ll)b * N_ + n) * 768 + 512))[lane];
    float2 f0 = __half22float2(*(__half2*)&v.x);
    float2 f1 = __half22float2(*(__half2*)&v.y);
    float2 f2 = __half22float2(*(__half2*)&v.z);
    float2 f3 = __half22float2(*(__half2*)&v.w);
    float dot = f0.x * mr[0] + f0.y * mr[1] + f1.x * mr[2] + f1.y * mr[3]
              + f2.x * mr[4] + f2.y * mr[5] + f3.x * mr[6] + f3.y * mr[7];
#pragma unroll
    for (int o = 16; o; o >>= 1) dot += __shfl_xor_sync(0xffffffffu, dot, o);
    if (lane == 0) {
        float sc = g_score[b * N_ + n] - 2.f * dot;  // + ||mu||^2 const dropped
        uint32_t u = __float_as_uint(sc);
        u ^= (uint32_t)(((int)u >> 31)) | 0x80000000u;  // monotone float->uint
        ((uint32_t*)g_score)[b * N_ + n] = u;
    }
}

// radix-select: one block per (batch, direction); warp-shfl scan (2 barriers/pass)
__global__ void select_kernel() {
    __shared__ uint32_t sv[N_];
    __shared__ int hist[256];
    __shared__ int wtot[8], woff[8];
    __shared__ int s_digit, s_k, s_cnt, s_base, s_total;
    int b = blockIdx.x, dir = blockIdx.y, t = threadIdx.x;  // 1024 threads
    int lane = t & 31, wid = t >> 5;
    for (int i = t; i < N_; i += 1024) sv[i] = ((const uint32_t*)g_score)[b * N_ + i];
    __syncthreads();

    uint32_t prefix = 0, pmask = 0;
    int k = M_;
    for (int pass = 0; pass < 4; pass++) {
        int shift = 24 - 8 * pass;
        if (t < 256) hist[t] = 0;
        __syncthreads();
        for (int i = t; i < N_; i += 1024) {
            uint32_t v = sv[i];
            if ((v & pmask) == prefix) atomicAdd(&hist[(v >> shift) & 255], 1);
        }
        __syncthreads();
        int val = 0, h = 0;
        if (t < 256) {
            h = hist[t]; val = h;
#pragma unroll
            for (int off = 1; off < 32; off <<= 1) {
                int nv = __shfl_up_sync(0xffffffffu, val, off);
                if (lane >= off) val += nv;
            }
            if (lane == 31) wtot[wid] = val;
        }
        __syncthreads();
        if (t == 0) {
            int acc = 0;
#pragma unroll
            for (int w = 0; w < 8; w++) { woff[w] = acc; acc += wtot[w]; }
            s_total = acc;
        }
        __syncthreads();
        if (t < 256) {
            int incl = val + woff[wid];
            int excl = incl - h;
            int total = s_total;
            if (dir == 0) {
                int above = total - incl, atLeast = total - excl;
                if (atLeast >= k && above < k) { s_digit = t; s_k = k - above; }
            } else {
                if (incl >= k && excl < k) { s_digit = t; s_k = k - excl; }
            }
        }
        __syncthreads();
        prefix |= ((uint32_t)s_digit) << shift;
        pmask |= 0xFFu << shift;
        k = s_k;
        __syncthreads();
    }
    uint32_t T = prefix;
    int keq = k;
    if (t == 0) s_cnt = 0;
    __syncthreads();
    int* dst = g_idx + dir * B_ * M_ + b * M_;
    for (int i = t; i < N_; i += 1024) {
        uint32_t v = sv[i];
        bool strict = (dir == 0) ? (v > T) : (v < T);
        if (strict) dst[atomicAdd(&s_cnt, 1)] = i;
    }
    __syncthreads();
    if (t == 0) { s_base = s_cnt; s_cnt = 0; }
    __syncthreads();
    for (int i = t; i < N_; i += 1024) {
        if (sv[i] == T) {
            int e = atomicAdd(&s_cnt, 1);
            if (e < keq) dst[s_base + e] = i;
        }
    }
}

__global__ void gather_kernel() {
    int side = blockIdx.z, b = blockIdx.y;
    int m = blockIdx.x * 8 + (threadIdx.x >> 5);
    int c8 = threadIdx.x & 31;
    int j = g_idx[side * B_ * M_ + b * M_ + m];
    uint4 v = ((const uint4*)(g_cat + ((ll)b * N_ + j) * 768 + 512))[c8];
    ((uint4*)(g_ctxh + (((ll)side * B_ + b) * M_ + m) * C_))[c8] = v;
}

// bqk[bz][m] = dot(K[side][b][m], bq_side) * log2e/16  (per-column S bias)
__global__ void bqk_kernel() {
    int bz = blockIdx.y, side = bz >> 4, b = bz & 15;
    int warp = threadIdx.x >> 5, lane = threadIdx.x & 31;
    int m = blockIdx.x * 8 + warp;
    const float* bq = g_bp + side * 256;
    float qr[8];
    {
        const float4* qp = (const float4*)bq;
        float4 q0 = qp[lane * 2], q1 = qp[lane * 2 + 1];
        qr[0] = q0.x; qr[1] = q0.y; qr[2] = q0.z; qr[3] = q0.w;
        qr[4] = q1.x; qr[5] = q1.y; qr[6] = q1.z; qr[7] = q1.w;
    }
    uint4 v = ((const uint4*)(g_Kh + (((ll)side * B_ + b) * M_ + m) * C_))[lane];
    float2 f0 = __half22float2(*(__half2*)&v.x);
    float2 f1 = __half22float2(*(__half2*)&v.y);
    float2 f2 = __half22float2(*(__half2*)&v.z);
    float2 f3 = __half22float2(*(__half2*)&v.w);
    float dot = f0.x * qr[0] + f0.y * qr[1] + f1.x * qr[2] + f1.y * qr[3]
              + f2.x * qr[4] + f2.y * qr[5] + f3.x * qr[6] + f3.y * qr[7];
#pragma unroll
    for (int o = 16; o; o >>= 1) dot += __shfl_xor_sync(0xffffffffu, dot, o);
    if (lane == 0) g_bqk[bz * M_ + m] = dot * (1.4426950408889634f / 16.f);
}

// pack_w: weights->fp16 (Wq transposed), biases->g_bp, zero-init l/xm/score/stats
__global__ void pack_w(const float* a0, const float* a1, const float* a2,
                       const float* a3, const float* a4, const float* a5,
                       const float* b0, const float* b1, const float* b2,
                       const float* b3, const float* b4, const float* b5) {
    int i = blockIdx.x * 256 + threadIdx.x;  // 393216 threads
    const float* p[6] = {a0, a1, a2, a3, a4, a5};
    int seg = i >> 16, loc = i & 65535;
    int src = (seg < 2) ? ((loc & 255) * 256 + (loc >> 8)) : loc;  // Wq stored transposed
    g_Wh[i] = __float2half_rn(p[seg][src]);
    if (i < 2 * B_ * N_) g_l[i] = 0.f;
    if (i < B_ * N_) g_score[i] = 0.f;
    if (i < B_ * C_) g_xm[i] = 0.f;
    if (i < C_) { g_sum[i] = 0.0; g_sumsq[i] = 0.0; }
    if (i < 1536) {
        const float* q[6] = {b0, b1, b2, b3, b4, b5};
        int grp = i >> 9, k = i & 511;
        g_bp[i] = q[(grp << 1) | (k >> 8)][k & 255];
    }
}

__global__ void combine_w(const float* __restrict__ Wf,
                          const float* __restrict__ Wo_s, const float* __restrict__ Wo_g,
                          const float* __restrict__ bf,
                          const float* __restrict__ bo_s, const float* __restrict__ bo_g) {
    int d = blockIdx.x, t = threadIdx.x;
    __shared__ float wf[512];
    wf[t] = Wf[d * 512 + t];
    wf[t + 256] = Wf[d * 512 + 256 + t];
    __syncthreads();
    float a0 = 0.f, a1 = 0.f;
#pragma unroll 4
    for (int e = 0; e < 256; e++) {
        a0 += wf[e] * Wo_s[e * 256 + t];
        a1 += wf[256 + e] * Wo_g[e * 256 + t];
    }
    g_W3[d * 768 + t] = __float2half_rn(a0);
    g_W3[d * 768 + 256 + t] = __float2half_rn(a1);
    g_W3[d * 768 + 512 + t] = __float2half_rn(wf[t] + wf[256 + t]);
    if (t == 0) {
        float bc = bf[d];
        for (int e = 0; e < 256; e++) bc += wf[e] * bo_s[e] + wf[256 + e] * bo_g[e];
        g_bc[d] = bc;
    }
}

__global__ void bn_finalize(const float* __restrict__ gamma, const float* __restrict__ beta) {
    int d = threadIdx.x;  // 256
    double cnt = (double)B_ * N_;
    double mu = g_sum[d] / cnt;
    double var = g_sumsq[d] / cnt - mu * mu;
    float w = gamma[d] * rsqrtf((float)var + EPS_);
    g_bnw[d] = w;
    g_bnb[d] = beta[d] - (float)mu * w;
}

__global__ void bn_final(float* __restrict__ out) {
    int i = blockIdx.x * 256 + threadIdx.x;  // N/4 per (d,b)
    int d = blockIdx.y, b = blockIdx.z;
    ll base = ((ll)b * C_ + d) * N_;
    uint2 raw = ((const uint2*)(g_Ph + base))[i];
    float2 f0 = __half22float2(*(__half2*)&raw.x);
    float2 f1 = __half22float2(*(__half2*)&raw.y);
    float w = g_bnw[d], bb = g_bnb[d];
    float4 o;
    o.x = fmaxf(f0.x * w + bb, 0.f);
    o.y = fmaxf(f0.y * w + bb, 0.f);
    o.z = fmaxf(f1.x * w + bb, 0.f);
    o.w = fmaxf(f1.y * w + bb, 0.f);
    ((float4*)(out + base))[i] = o;
}

// ---------------- fp16 TN GEMM: 3-stage cp.async pipeline ----------------
// EPI: 0 none, 1 ex2(h2)+rowsum (scale pre-folds log2e), 2 div-by-l
__device__ __forceinline__ void load_stage(uint32_t sb, const __half* A, const __half* Bg,
                                           int row0, int col0, int lda, int ldb,
                                           int k0, int tid) {
#pragma unroll
    for (int r = 0; r < 4; r++) {
        int lin = tid + r * 256;
        int row = lin >> 3, f4 = lin & 7;
        uint32_t so = (uint32_t)((row * 8 + (f4 ^ (row & 7))) * 16);
        cp16(sb + so, A + (ll)(row0 + row) * lda + k0 + f4 * 8);
        cp16(sb + 16384 + so, Bg + (ll)(col0 + row) * ldb + k0 + f4 * 8);
    }
}

template <int BIAS, int EPI, bool STATS>
__global__ __launch_bounds__(256, 2)
void gemm_tn(const __half* __restrict__ A, ll sA, ll sA2, int lda,
             const __half* __restrict__ Bg, ll sB, ll sB2, int ldb,
             __half* __restrict__ Cm, ll sC, ll sC2, int ldc, int Kd,
             const float* __restrict__ bias, int biasStr, int biasBzStr,
             float scale, double* stS, double* stQ,
             float* lrow, ll sL) {
    extern __shared__ char smc[];
    const uint32_t smu = (uint32_t)__cvta_generic_to_shared(smc);
    const int bz = blockIdx.z, side = bz >> 4, b = bz & 15;
    A += (ll)b * sA + (ll)side * sA2;
    Bg += (ll)b * sB + (ll)side * sB2;
    Cm += (ll)b * sC + (ll)side * sC2;
    if (BIAS) bias += (ll)side * biasStr + (ll)b * biasBzStr;
    if (EPI) lrow += (ll)bz * sL;
    const int row0 = blockIdx.y * 128, col0 = blockIdx.x * 128;
    const int tid = threadIdx.x, lane = tid & 31, warp = tid >> 5;
    const int wm = warp >> 2, wn = warp & 3;
    const int rA = lane & 15, selA = lane >> 4;
    const int tb = lane & 15, rB = tb & 7, midB = tb >> 3;

    float acc[4][4][4];
#pragma unroll
    for (int i = 0; i < 4; i++)
#pragma unroll
        for (int j = 0; j < 4; j++)
#pragma unroll
            for (int q = 0; q < 4; q++) acc[i][j][q] = 0.f;

    const int nT = Kd / 64;
    load_stage(smu, A, Bg, row0, col0, lda, ldb, 0, tid); cp_commit();
    load_stage(smu + 32768, A, Bg, row0, col0, lda, ldb, 64, tid); cp_commit();

    for (int t = 0; t < nT; t++) {
        if (t + 2 < nT)
            load_stage(smu + (uint32_t)(((t + 2) % 3) * 32768), A, Bg,
                       row0, col0, lda, ldb, (t + 2) * 64, tid);
        cp_commit();
        cp_wait<2>();
        __syncthreads();

        uint32_t Au = smu + (uint32_t)((t % 3) * 32768);
        uint32_t Bu = Au + 16384;
#pragma unroll
        for (int kt = 0; kt < 4; kt++) {
            uint32_t af[4][4], bf4[4][2];
#pragma unroll
            for (int mt = 0; mt < 4; mt++) {
                int row = wm * 64 + mt * 16 + rA;
                int u = kt * 2 + selA;
                ldsm_x4(af[mt], Au + (uint32_t)((row * 8 + (u ^ (row & 7))) * 16));
            }
#pragma unroll
            for (int nt = 0; nt < 4; nt++) {
                int row = wn * 32 + nt * 8 + rB;
                int u = kt * 2 + midB;
                ldsm_x2(bf4[nt], Bu + (uint32_t)((row * 8 + (u ^ (row & 7))) * 16));
            }
#pragma unroll
            for (int mt = 0; mt < 4; mt++)
#pragma unroll
                for (int nt = 0; nt < 4; nt++)
                    mma_f16(acc[mt][nt], af[mt], bf4[nt]);
        }
        __syncthreads();
    }

    const int gr = lane >> 2, gc = (lane & 3) * 2;
#pragma unroll
    for (int mt = 0; mt < 4; mt++) {
        int r0 = row0 + wm * 64 + mt * 16 + gr;
        float inv0 = 1.f, inv1 = 1.f;
        if (EPI == 2) { inv0 = 1.f / lrow[r0]; inv1 = 1.f / lrow[r0 + 8]; }
        float s0 = 0.f, q0 = 0.f, s1 = 0.f, q1 = 0.f;
#pragma unroll
        for (int nt = 0; nt < 4; nt++) {
            int col = col0 + wn * 32 + nt * 8 + gc;
            float v0x = acc[mt][nt][0] * scale, v0y = acc[mt][nt][1] * scale;
            float v1x = acc[mt][nt][2] * scale, v1y = acc[mt][nt][3] * scale;
            if (BIAS == 1) {
                float bx = bias[col], by = bias[col + 1];
                v0x += bx; v0y += by; v1x += bx; v1y += by;
            } else if (BIAS == 2) {
                float b0v = bias[r0], b1v = bias[r0 + 8];
                v0x += b0v; v0y += b0v; v1x += b1v; v1y += b1v;
            }
            if (EPI == 1) {
                __half2 h0 = __floats2half2_rn(v0x, v0y);
                __half2 h1 = __floats2half2_rn(v1x, v1y);
                uint32_t e0 = ex2_h2(*(uint32_t*)&h0);
                uint32_t e1 = ex2_h2(*(uint32_t*)&h1);
                float2 f0 = __half22float2(*(__half2*)&e0);
                float2 f1 = __half22float2(*(__half2*)&e1);
                s0 += f0.x + f0.y; s1 += f1.x + f1.y;
                *(uint32_t*)(Cm + (ll)r0 * ldc + col) = e0;
                *(uint32_t*)(Cm + (ll)(r0 + 8) * ldc + col) = e1;
                continue;
            }
            if (EPI == 2) { v0x *= inv0; v0y *= inv0; v1x *= inv1; v1y *= inv1; }
            if (STATS) {
                s0 += v0x + v0y; q0 += v0x * v0x + v0y * v0y;
                s1 += v1x + v1y; q1 += v1x * v1x + v1y * v1y;
            }
            *(__half2*)(Cm + (ll)r0 * ldc + col) = __floats2half2_rn(v0x, v0y);
            *(__half2*)(Cm + (ll)(r0 + 8) * ldc + col) = __floats2half2_rn(v1x, v1y);
        }
        if (EPI == 1) {
            s0 += __shfl_xor_sync(0xffffffffu, s0, 1); s0 += __shfl_xor_sync(0xffffffffu, s0, 2);
            s1 += __shfl_xor_sync(0xffffffffu, s1, 1); s1 += __shfl_xor_sync(0xffffffffu, s1, 2);
            if ((lane & 3) == 0) {
                atomicAdd(&lrow[r0], s0);
                atomicAdd(&lrow[r0 + 8], s1);
            }
        }
        if (STATS) {
            s0 += __shfl_xor_sync(0xffffffffu, s0, 1); s0 += __shfl_xor_sync(0xffffffffu, s0, 2);
            q0 += __shfl_xor_sync(0xffffffffu, q0, 1); q0 += __shfl_xor_sync(0xffffffffu, q0, 2);
            s1 += __shfl_xor_sync(0xffffffffu, s1, 1); s1 += __shfl_xor_sync(0xffffffffu, s1, 2);
            q1 += __shfl_xor_sync(0xffffffffu, q1, 1); q1 += __shfl_xor_sync(0xffffffffu, q1, 2);
            if ((lane & 3) == 0) {
                atomicAdd(&stS[r0], (double)s0);
                atomicAdd(&stQ[r0], (double)q0);
                atomicAdd(&stS[r0 + 8], (double)s1);
                atomicAdd(&stQ[r0 + 8], (double)q1);
            }
        }
    }
}

template <int BIAS, int EPI, bool STATS>
static void launch_tn(const __half* A, ll sA, ll sA2, int lda,
                      const __half* Bg, ll sB, ll sB2, int ldb,
                      __half* Cm, ll sC, ll sC2, int ldc,
                      int Md, int Nd, int Kd,
                      const float* bias, int biasStr, int biasBzStr,
                      float scale, int batch,
                      double* stS, double* stQ, float* lrow, ll sL) {
    cudaFuncSetAttribute(gemm_tn<BIAS, EPI, STATS>,
                         cudaFuncAttributeMaxDynamicSharedMemorySize, 98304);
    dim3 grid(Nd / 128, Md / 128, batch);
    gemm_tn<BIAS, EPI, STATS><<<grid, 256, 98304>>>(
        A, sA, sA2, lda, Bg, sB, sB2, ldb, Cm, sC, sC2, ldc, Kd,
        bias, biasStr, biasBzStr, scale, stS, stQ, lrow, sL);
}

// ---------------- driver ----------------
extern "C" void kernel_launch(void* const* d_in, const int* in_sizes, int n_in,
                              void* d_out, int out_size) {
    const float* x = (const float*)d_in[0];
    int pb = (n_in > 1 && in_sizes[1] == 1) ? 2 : 1;
    const float* P[20];
    for (int i = 0; i < 20; i++) P[i] = (const float*)d_in[pb + i];
    float* out = (float*)d_out;

    __half *cat, *ctxh, *K2h, *Kh, *Vth, *Sh, *Ph, *Wh, *W3;
    float *bp, *bc, *bqk, *lptr;
    double *stS, *stQ;
    cudaGetSymbolAddress((void**)&cat, g_cat);
    cudaGetSymbolAddress((void**)&ctxh, g_ctxh);
    cudaGetSymbolAddress((void**)&K2h, g_K2h);
    cudaGetSymbolAddress((void**)&Kh, g_Kh);
    cudaGetSymbolAddress((void**)&Vth, g_Vth);
    cudaGetSymbolAddress((void**)&Sh, g_Sh);
    cudaGetSymbolAddress((void**)&Ph, g_Ph);
    cudaGetSymbolAddress((void**)&Wh, g_Wh);
    cudaGetSymbolAddress((void**)&W3, g_W3);
    cudaGetSymbolAddress((void**)&bp, g_bp);
    cudaGetSymbolAddress((void**)&bc, g_bc);
    cudaGetSymbolAddress((void**)&bqk, g_bqk);
    cudaGetSymbolAddress((void**)&lptr, g_l);
    cudaGetSymbolAddress((void**)&stS, g_sum);
    cudaGetSymbolAddress((void**)&stQ, g_sumsq);

    const int CC = C_ * C_;
    const float LOG2E = 1.4426950408889634f;

    pack_w<<<1536, 256>>>(P[0], P[8], P[2], P[10], P[4], P[12],
                          P[1], P[9], P[3], P[11], P[5], P[13]);  // + zero init
    transpose_kernel<<<dim3(N_ / 32, C_ / 32, B_), dim3(32, 8)>>>(x);
    score2_kernel<<<dim3(N_ / 8, B_), 256>>>();
    select_kernel<<<dim3(B_, 2), 1024>>>();
    gather_kernel<<<dim3(M_ / 8, B_, 2), 256>>>();
    combine_w<<<256, 256>>>(P[16], P[6], P[14], P[17], P[7], P[15]);

    // K = ctx·Wk^T + bk
    launch_tn<1, 0, false>(ctxh, (ll)M_ * C_, (ll)B_ * M_ * C_, C_,
                           Wh + 2 * CC, 0, CC, C_,
                           Kh, (ll)M_ * C_, (ll)B_ * M_ * C_, C_,
                           M_, C_, C_, bp + 512, 256, 0, 1.f, 2 * B_,
                           nullptr, nullptr, nullptr, 0);
    // K'' = K·Wq  (Wq packed transposed)
    launch_tn<0, 0, false>(Kh, (ll)M_ * C_, (ll)B_ * M_ * C_, C_,
                           Wh, 0, CC, C_,
                           K2h, (ll)M_ * C_, (ll)B_ * M_ * C_, C_,
                           M_, C_, C_, nullptr, 0, 0, 1.f, 2 * B_,
                           nullptr, nullptr, nullptr, 0);
    bqk_kernel<<<dim3(M_ / 8, 2 * B_), 256>>>();
    // V^T
    launch_tn<2, 0, false>(Wh + 4 * CC, 0, CC, C_,
                           ctxh, (ll)M_ * C_, (ll)B_ * M_ * C_, C_,
                           Vth, (ll)C_ * M_, (ll)B_ * C_ * M_, M_,
                           C_, M_, C_, bp + 1024, 256, 0, 1.f, 2 * B_,
                           nullptr, nullptr, nullptr, 0);
    // S~ = 2^((x·K''^T + bqK)·log2e/16), row sums
    launch_tn<1, 1, false>(cat + 512, (ll)N_ * 768, 0, 768,
                           K2h, (ll)M_ * C_, (ll)B_ * M_ * C_, C_,
                           Sh, (ll)N_ * M_, (ll)B_ * N_ * M_, M_,
                           N_, M_, C_, bqk, B_ * M_, M_, LOG2E / 16.f, 2 * B_,
                           nullptr, nullptr, lptr, N_);
    // Y = (S~·V)/l -> cat slots
    launch_tn<0, 2, false>(Sh, (ll)N_ * M_, (ll)B_ * N_ * M_, M_,
                           Vth, (ll)C_ * M_, (ll)B_ * C_ * M_, M_,
                           cat, (ll)N_ * 768, 256, 768,
                           N_, C_, M_, nullptr, 0, 0, 1.f, 2 * B_,
                           nullptr, nullptr, lptr, N_);
    // fuse + BN stats
    launch_tn<2, 0, true>(W3, 0, 0, 768,
                          cat, (ll)N_ * 768, 0, 768,
                          Ph, (ll)C_ * N_, 0, N_,
                          C_, N_, 768, bc, 0, 0, 1.f, B_, stS, stQ, nullptr, 0);

    bn_finalize<<<1, 256>>>(P[18], P[19]);
    bn_final<<<dim3(N_ / 1024, C_, B_), 256>>>(out);
}